// round 9
// baseline (speedup 1.0000x reference)
#include <cuda_runtime.h>
#include <stdint.h>

// Problem constants (match reference)
#define HOP        160
#define FFT        1024
#define NUM_LABELS 72
#define BATCH      4
#define TLEN       240000
#define PAD        (FFT / 2)           // 512
#define LPAD       (TLEN + 2 * PAD)    // 241024
#define NOUT       ((LPAD - FFT) / HOP + 1)  // 1501

#define W_RUN          8
#define WARPS_PER_CTA  4
#define BLOCK          (WARPS_PER_CTA * 32)
#define RUNS_PER_B     ((NOUT + W_RUN - 1) / W_RUN)                        // 188
#define CTAS_X         ((RUNS_PER_B + WARPS_PER_CTA - 1) / WARPS_PER_CTA)  // 47

// Interior runs touch only unpadded indices in [0, TLEN).
// run>=1: w0=8 -> first unpadded idx 8*160-512 = 768 >= 0.
// run<=186: last window w=1495 -> 1495*160+511 = 239711 < 240000.
#define RUN_INT_LO 1
#define RUN_INT_HI 186

__device__ __forceinline__ int reflect_idx(int j)
{
    int o = j - PAD;
    if (o < 0) o = -o;
    else if (o >= TLEN) o = 2 * (TLEN - 1) - o;
    return o;
}

// Warp-wide argmax over 72 bins, lowest-label tie-break (matches jnp.argmax):
// pack count<<7 | (127-label), take max.
__device__ __forceinline__ void scan_and_write(const int* __restrict__ h,
                                               float* __restrict__ orow,
                                               int w, int lane)
{
    int p = (h[lane] << 7) | (127 - lane);
    int q = (h[lane + 32] << 7) | (127 - (lane + 32));
    p = max(p, q);
    if (lane < NUM_LABELS - 64) {
        q = (h[lane + 64] << 7) | (127 - (lane + 64));
        p = max(p, q);
    }
    p = __reduce_max_sync(0xFFFFFFFFu, p);   // REDUX.MAX
    if (lane == 0) orow[w] = (float)(127 - (p & 127));
}

__global__ void __launch_bounds__(BLOCK)
label_majority_warpslide8(const int* __restrict__ lbl, float* __restrict__ out)
{
    __shared__ int hist[WARPS_PER_CTA][NUM_LABELS];

    const int lane = threadIdx.x & 31;
    const int wid  = threadIdx.x >> 5;
    const int b    = blockIdx.y;
    const int run  = blockIdx.x * WARPS_PER_CTA + wid;
    if (run >= RUNS_PER_B) return;

    const int w0 = run * W_RUN;

    const int* __restrict__ row  = lbl + (size_t)b * TLEN;
    float* __restrict__     orow = out + (size_t)b * NOUT;
    int* __restrict__       h    = hist[wid];

    // zero private histogram
    h[lane] = 0;
    h[lane + 32] = 0;
    if (lane < NUM_LABELS - 64) h[lane + 64] = 0;
    __syncwarp();

    if (run >= RUN_INT_LO && run <= RUN_INT_HI) {
        // ================= interior fast path (branch-free, vectorized) ====
        const int* __restrict__ base = row + (w0 * HOP - PAD);  // int4-aligned

        // ---- build window w0: 8 x int4 per lane (high MLP), 32 atomics ----
        int4 v[8];
        #pragma unroll
        for (int k = 0; k < 8; k++)
            v[k] = *(const int4*)(base + k * 128 + lane * 4);
        #pragma unroll
        for (int k = 0; k < 8; k++) {
            atomicAdd(&h[v[k].x], 1);
            atomicAdd(&h[v[k].y], 1);
            atomicAdd(&h[v[k].z], 1);
            atomicAdd(&h[v[k].w], 1);
        }
        __syncwarp();

        // ---- slide: prefetch labels, scan previous window, then update ----
        #pragma unroll
        for (int i = 1; i < W_RUN; i++) {
            const int* __restrict__ ob = base + (i - 1) * HOP;  // leaving
            const int* __restrict__ nb = ob + FFT;              // entering
            int4 o4 = *(const int4*)(ob + lane * 4);
            int  os = ob[128 + lane];
            int4 n4 = *(const int4*)(nb + lane * 4);
            int  ns = nb[128 + lane];

            scan_and_write(h, orow, w0 + i - 1, lane);
            __syncwarp();   // scan reads done before updates

            atomicSub(&h[o4.x], 1); atomicSub(&h[o4.y], 1);
            atomicSub(&h[o4.z], 1); atomicSub(&h[o4.w], 1);
            atomicSub(&h[os], 1);
            atomicAdd(&h[n4.x], 1); atomicAdd(&h[n4.y], 1);
            atomicAdd(&h[n4.z], 1); atomicAdd(&h[n4.w], 1);
            atomicAdd(&h[ns], 1);
            __syncwarp();   // updates visible before next scan
        }
        scan_and_write(h, orow, w0 + W_RUN - 1, lane);
    } else {
        // ================= edge path (reflect handling, scalar) ============
        const int start = w0 * HOP;
        #pragma unroll
        for (int k = 0; k < FFT / 32; k++) {
            int j = start + lane + k * 32;
            atomicAdd(&h[row[reflect_idx(j)]], 1);
        }
        __syncwarp();
        scan_and_write(h, orow, w0, lane);

        #pragma unroll
        for (int i = 1; i < W_RUN; i++) {
            const int w = w0 + i;
            if (w >= NOUT) break;
            __syncwarp();
            const int bidx = (w - 1) * HOP;
            #pragma unroll
            for (int k = 0; k < HOP / 32; k++) {
                int jo = bidx + lane + k * 32;
                int jn = bidx + FFT + lane + k * 32;
                atomicSub(&h[row[reflect_idx(jo)]], 1);
                atomicAdd(&h[row[reflect_idx(jn)]], 1);
            }
            __syncwarp();
            scan_and_write(h, orow, w, lane);
        }
    }
}

extern "C" void kernel_launch(void* const* d_in, const int* in_sizes, int n_in,
                              void* d_out, int out_size)
{
    const int* lbl = (const int*)d_in[0];   // [B, T] int32
    // d_in[1]: all-ones conv weight — irrelevant (window sum == histogram).
    float* out = (float*)d_out;             // [B, NOUT], compared as float32

    dim3 grid(CTAS_X, BATCH);
    label_majority_warpslide8<<<grid, BLOCK>>>(lbl, out);
}

// round 10
// speedup vs baseline: 1.0332x; 1.0332x over previous
#include <cuda_runtime.h>
#include <stdint.h>
#include <limits.h>

// Problem constants (match reference)
#define HOP        160
#define FFT        1024
#define NUM_LABELS 72
#define BATCH      4
#define TLEN       240000
#define PAD        (FFT / 2)           // 512
#define LPAD       (TLEN + 2 * PAD)    // 241024
#define NOUT       ((LPAD - FFT) / HOP + 1)  // 1501

// Segment decomposition: window w covers padded [160w, 160w+1024)
// = segments [5w, 5w+32) with 32-element segments.
#define SEGLEN        32
#define SEGS_PER_WIN  32                   // 1024/32
#define WINS_PER_CTA  32
#define SEGS_PER_CTA  (5 * WINS_PER_CTA + 27)   // 187
#define NCOLS         (NUM_LABELS / 4)     // 18 packed u32 columns (4 bins each)
#define W_PER_WARP    4
#define WARPS         8
#define BLOCK         (WARPS * 32)
#define CTAS_X        ((NOUT + WINS_PER_CTA - 1) / WINS_PER_CTA)   // 47

__device__ __forceinline__ int reflect_idx(int j)
{
    int o = j - PAD;
    if (o < 0) o = -o;                          // left reflect (excl. edge)
    else if (o >= TLEN) o = 2 * (TLEN - 1) - o; // right reflect
    return o;                                    // stays in [0, TLEN) for all j used
}

// Argmax over this warp's packed accumulators (lanes 0..17 own bins 4c..4c+3),
// lowest-label tie-break (matches jnp.argmax).
__device__ __forceinline__ void scan_write(uint32_t accE, uint32_t accO,
                                           int lane, float* __restrict__ orow,
                                           int w)
{
    int p = INT_MIN;
    if (lane < NCOLS) {
        int b0 = 4 * lane;
        int c0 = (int)(accE & 0xFFFFu);   // bin b0
        int c2 = (int)(accE >> 16);       // bin b0+2
        int c1 = (int)(accO & 0xFFFFu);   // bin b0+1
        int c3 = (int)(accO >> 16);       // bin b0+3
        p =         (c0 << 7) | (127 - b0);
        p = max(p, (c1 << 7) | (127 - (b0 + 1)));
        p = max(p, (c2 << 7) | (127 - (b0 + 2)));
        p = max(p, (c3 << 7) | (127 - (b0 + 3)));
    }
    p = __reduce_max_sync(0xFFFFFFFFu, p);
    if (lane == 0 && w < NOUT)
        orow[w] = (float)(127 - (p & 127));
}

__global__ void __launch_bounds__(BLOCK)
label_majority_seghist(const int* __restrict__ lbl, float* __restrict__ out)
{
    // Column-major packed segment histograms: sh[col*SEGS_PER_CTA + seg].
    // Pitch 187 is odd -> phase-2 column reads are bank-conflict-free.
    __shared__ uint32_t sh[NCOLS * SEGS_PER_CTA];

    const int tid  = threadIdx.x;
    const int lane = tid & 31;
    const int wid  = tid >> 5;
    const int b    = blockIdx.y;
    const int w0   = blockIdx.x * WINS_PER_CTA;
    const int gseg0 = 5 * w0;

    const int* __restrict__ row  = lbl + (size_t)b * TLEN;
    float* __restrict__     orow = out + (size_t)b * NOUT;

    // zero segment histograms
    #pragma unroll
    for (int i = tid; i < NCOLS * SEGS_PER_CTA; i += BLOCK)
        sh[i] = 0;
    __syncthreads();

    // ================= phase 1: per-segment packed histograms ==============
    // One warp-iteration per segment: 32 coalesced loads + 32 smem atomics
    // into <=18 distinct words (bins byte-packed, 4 per u32; per-segment
    // bin count <=32 so bytes never carry).
    for (int s = wid; s < SEGS_PER_CTA; s += WARPS) {
        int j = (gseg0 + s) * SEGLEN + lane;    // padded index
        int v = row[reflect_idx(j)];
        atomicAdd(&sh[(v >> 2) * SEGS_PER_CTA + s], 1u << ((v & 3) * 8));
    }
    __syncthreads();

    // ================= phase 2: sliding window sums (no atomics) ===========
    // Warp 'wid' handles windows w0 + 4*wid + i, i=0..3.
    // Lane c (<18) owns bins 4c..4c+3, accumulating u8x4 -> u16x2 pairs:
    //   accE holds bins (4c, 4c+2), accO holds (4c+1, 4c+3); sums <=1024.
    const int wrel0 = wid * W_PER_WARP;
    const uint32_t* __restrict__ col = sh + lane * SEGS_PER_CTA;
    const int srel0 = 5 * wrel0;

    uint32_t accE = 0, accO = 0;
    if (lane < NCOLS) {
        #pragma unroll
        for (int k = 0; k < SEGS_PER_WIN; k++) {
            uint32_t v = col[srel0 + k];
            accE += v & 0x00FF00FFu;
            accO += (v >> 8) & 0x00FF00FFu;
        }
    }
    scan_write(accE, accO, lane, orow, w0 + wrel0);

    #pragma unroll
    for (int i = 1; i < W_PER_WARP; i++) {
        if (lane < NCOLS) {
            const int so = srel0 + 5 * (i - 1);           // 5 leaving segments
            #pragma unroll
            for (int k = 0; k < 5; k++) {
                uint32_t vo = col[so + k];
                uint32_t vn = col[so + SEGS_PER_WIN + k];  // 5 entering
                accE -= vo & 0x00FF00FFu;
                accO -= (vo >> 8) & 0x00FF00FFu;
                accE += vn & 0x00FF00FFu;
                accO += (vn >> 8) & 0x00FF00FFu;
            }
        }
        scan_write(accE, accO, lane, orow, w0 + wrel0 + i);
    }
}

extern "C" void kernel_launch(void* const* d_in, const int* in_sizes, int n_in,
                              void* d_out, int out_size)
{
    const int* lbl = (const int*)d_in[0];   // [B, T] int32
    // d_in[1]: all-ones conv weight — irrelevant (window sum == histogram).
    float* out = (float*)d_out;             // [B, NOUT], compared as float32

    dim3 grid(CTAS_X, BATCH);
    label_majority_seghist<<<grid, BLOCK>>>(lbl, out);
}